// round 15
// baseline (speedup 1.0000x reference)
#include <cuda_runtime.h>
#include <cuda_bf16.h>
#include <cstdint>
#include <math.h>

#define NSPK 512
#define UU   32
#define DD   512
#define NU   (NSPK*UU)
#define EPS  1e-8f

// ---------------- device scratch (no cudaMalloc allowed) ----------------
__device__ __nv_bfloat16 g_Ebf[(size_t)NU * DD];   // normalized embeddings, bf16 (16 MB)
__device__ __nv_bfloat16 g_Cbf[NSPK * DD];         // normalized centroids, bf16 (0.5 MB)
__device__ float         g_part[256];              // per-GEMM-block partial sums
__device__ int           g_ctr;                    // zero-init completion counter

// ---------------- PTX helpers ----------------
static __device__ __forceinline__ uint32_t smem_u32(const void* p) {
    uint32_t a;
    asm("{ .reg .u64 t; cvta.to.shared.u64 t, %1; cvt.u32.u64 %0, t; }" : "=r"(a) : "l"(p));
    return a;
}
static __device__ __forceinline__ void ldsm_x4(uint32_t& r0, uint32_t& r1,
                                               uint32_t& r2, uint32_t& r3, uint32_t addr) {
    asm volatile("ldmatrix.sync.aligned.m8n8.x4.shared.b16 {%0,%1,%2,%3}, [%4];"
                 : "=r"(r0), "=r"(r1), "=r"(r2), "=r"(r3) : "r"(addr));
}
static __device__ __forceinline__ void mma16816(float& d0, float& d1, float& d2, float& d3,
                                                uint32_t a0, uint32_t a1, uint32_t a2, uint32_t a3,
                                                uint32_t b0, uint32_t b1) {
    asm volatile(
        "mma.sync.aligned.m16n8k16.row.col.f32.bf16.bf16.f32 "
        "{%0,%1,%2,%3}, {%4,%5,%6,%7}, {%8,%9}, {%0,%1,%2,%3};"
        : "+f"(d0), "+f"(d1), "+f"(d2), "+f"(d3)
        : "r"(a0), "r"(a1), "r"(a2), "r"(a3), "r"(b0), "r"(b1));
}
static __device__ __forceinline__ void cpa16(uint32_t dst, const void* gsrc) {
    unsigned long long g = (unsigned long long)__cvta_generic_to_global(gsrc);
    asm volatile("cp.async.cg.shared.global [%0], [%1], 16;" :: "r"(dst), "l"(g));
}

// ---------------------------------------------------------------------------
// Kernel P: per-speaker pass (centroid+norm fused, packed bf16 writes)
// grid = 512, 256 threads, 64KB dynamic smem
// ---------------------------------------------------------------------------
__global__ void __launch_bounds__(256, 1) prep_kernel(const float* __restrict__ emb) {
    extern __shared__ float s[];
    __shared__ float red[9];
    const int n = blockIdx.x, tid = threadIdx.x;
    const int w = tid >> 5, lane = tid & 31;

    const float4* src = reinterpret_cast<const float4*>(emb) + (size_t)n * 4096;
    float4* s4 = reinterpret_cast<float4*>(s);
    #pragma unroll
    for (int i = 0; i < 16; i++) s4[tid + i * 256] = src[tid + i * 256];
    __syncthreads();

    float c0 = 0.f, c1 = 0.f;
    #pragma unroll
    for (int u = 0; u < UU; u++) {
        c0 += s[u * DD + tid];
        c1 += s[u * DD + tid + 256];
    }
    c0 *= (1.0f / UU); c1 *= (1.0f / UU);
    float sq = fmaf(c0, c0, c1 * c1);
    #pragma unroll
    for (int o = 16; o > 0; o >>= 1) sq += __shfl_xor_sync(0xffffffffu, sq, o);
    if (lane == 0) red[w] = sq;
    __syncthreads();
    if (tid == 0) {
        float t = 0.f;
        #pragma unroll
        for (int i = 0; i < 8; i++) t += red[i];
        red[8] = 1.0f / fmaxf(sqrtf(t), EPS);
    }
    __syncthreads();
    const float invc = red[8];
    g_Cbf[n * DD + tid]       = __float2bfloat16(c0 * invc);
    g_Cbf[n * DD + tid + 256] = __float2bfloat16(c1 * invc);

    for (int u = w; u < UU; u += 8) {
        const float4* rowp = reinterpret_cast<const float4*>(s + u * DD);
        float4 v[4]; float ss = 0.f;
        #pragma unroll
        for (int j = 0; j < 4; j++) {
            v[j] = rowp[lane + j * 32];
            ss = fmaf(v[j].x, v[j].x, ss);
            ss = fmaf(v[j].y, v[j].y, ss);
            ss = fmaf(v[j].z, v[j].z, ss);
            ss = fmaf(v[j].w, v[j].w, ss);
        }
        #pragma unroll
        for (int o = 16; o > 0; o >>= 1) ss += __shfl_xor_sync(0xffffffffu, ss, o);
        const float inv = 1.0f / fmaxf(sqrtf(ss), EPS);
        uint2* dst = reinterpret_cast<uint2*>(g_Ebf + ((size_t)n * UU + u) * DD);
        #pragma unroll
        for (int j = 0; j < 4; j++) {
            __nv_bfloat162 lo = __floats2bfloat162_rn(v[j].x * inv, v[j].y * inv);
            __nv_bfloat162 hi = __floats2bfloat162_rn(v[j].z * inv, v[j].w * inv);
            uint2 pk;
            pk.x = *reinterpret_cast<uint32_t*>(&lo);
            pk.y = *reinterpret_cast<uint32_t*>(&hi);
            dst[lane + j * 32] = pk;
        }
    }
}

// ---------------------------------------------------------------------------
// Kernel G: HMMA GEMM, streamed K-slices, 2 CTAs/SM.
// Block = 64 rows. N in 4 chunks of 128 spk; K in 4 slices of 128.
// Round (nh, ks): A slice 64x128 (16KB) + B slice 128x128 (32KB), dbl-buffered
// (2 x 48KB = 96KB). grid = 256, 256 threads = 8 warps: 2(M) x 4(N), warp
// tile 32x32 (256 B/MMA). Shift-free softmax, fused final reduction.
// Rows/slices are 256B in smem; swizzle: 16B-chunk ^= row&7.
// ---------------------------------------------------------------------------
#define STAGE   49152
#define SMB_OFF 16384
#define SM_TOT  98304

static __device__ __forceinline__ void load_round(uint32_t sb, int t, int tid, int bi) {
    const int nh = t >> 2, ks = t & 3;
    const uint32_t Ab = sb + (uint32_t)(t & 1) * STAGE;
    const uint32_t Bb = Ab + SMB_OFF;
    // A slice: 64 rows x 128 k = 1024 16B units
    #pragma unroll
    for (int it = 0; it < 4; it++) {
        const int u = tid + it * 256;
        const int r = u >> 4, c = u & 15;
        cpa16(Ab + (uint32_t)(r * 256 + ((c ^ (r & 7)) << 4)),
              g_Ebf + ((size_t)(bi * 64 + r)) * DD + ks * 128 + c * 8);
    }
    // B slice: 128 spk x 128 k = 2048 16B units
    #pragma unroll
    for (int it = 0; it < 8; it++) {
        const int u = tid + it * 256;
        const int r = u >> 4, c = u & 15;
        cpa16(Bb + (uint32_t)(r * 256 + ((c ^ (r & 7)) << 4)),
              g_Cbf + ((size_t)(nh * 128 + r)) * DD + ks * 128 + c * 8);
    }
    asm volatile("cp.async.commit_group;" ::: "memory");
}

__global__ void __launch_bounds__(256, 2)
gemm_loss_kernel(const float* __restrict__ wp, const float* __restrict__ bp,
                 float* __restrict__ out) {
    extern __shared__ char smem[];
    __shared__ int lastflag;
    const uint32_t sb = smem_u32(smem);
    const int tid = threadIdx.x, wid = tid >> 5, lane = tid & 31;
    const int bi = blockIdx.x;
    const int wm = wid >> 2;       // row half (32 rows)
    const int wn = wid & 3;        // 32-col stripe within 128-spk chunk
    const int l7 = lane & 7;

    // ldmatrix per-thread offsets (row stride 256B)
    const uint32_t aoff0 = (uint32_t)(wm * 32 + (lane & 15)) * 256;          // mt=0
    const uint32_t aoff1 = aoff0 + 16 * 256;                                  // mt=1
    const int cbA = lane >> 4;              // A k-chunk select (16B units)
    const int khB = (lane >> 3) & 1;        // B k-chunk select
    const uint32_t boff0 = (uint32_t)(wn * 32 + (lane >> 4) * 8 + l7) * 256; // nt 0/1
    const uint32_t boff1 = boff0 + 16 * 256;                                  // nt 2/3

    // diagonal bookkeeping (warp-uniform speaker index)
    const int diag = bi * 2 + wm;           // this warp's rows' speaker
    const int nh_d = diag >> 7;             // which 128-spk chunk
    const int cc = diag & 127;
    const int dwn = cc >> 5;                // which 32-col stripe
    const int dj = cc & 31;
    const int dnt = dj >> 3, down = (dj & 7) >> 1, de = dj & 1;

    float os[4], od[4];
    #pragma unroll
    for (int i = 0; i < 4; i++) { os[i] = 0.f; od[i] = 0.f; }
    float acc[2][4][4];

    const float Wv = wp[0], Bv = bp[0];

    load_round(sb, 0, tid, bi);
    load_round(sb, 1, tid, bi);

    for (int t = 0; t < 16; t++) {
        if ((t & 3) == 0) {
            #pragma unroll
            for (int mt = 0; mt < 2; mt++)
                #pragma unroll
                for (int nt = 0; nt < 4; nt++)
                    #pragma unroll
                    for (int e = 0; e < 4; e++) acc[mt][nt][e] = 0.f;
        }
        if (t < 15) asm volatile("cp.async.wait_group 1;" ::: "memory");
        else        asm volatile("cp.async.wait_group 0;" ::: "memory");
        __syncthreads();

        const uint32_t Ab = sb + (uint32_t)(t & 1) * STAGE;
        const uint32_t Bb = Ab + SMB_OFF;

        #pragma unroll
        for (int kk = 0; kk < 8; kk++) {
            const int cb = kk * 2;
            uint32_t a[2][4], b[4][2];
            ldsm_x4(a[0][0], a[0][1], a[0][2], a[0][3],
                    Ab + aoff0 + ((uint32_t)((cb + cbA) ^ l7) << 4));
            ldsm_x4(a[1][0], a[1][1], a[1][2], a[1][3],
                    Ab + aoff1 + ((uint32_t)((cb + cbA) ^ l7) << 4));
            ldsm_x4(b[0][0], b[0][1], b[1][0], b[1][1],
                    Bb + boff0 + ((uint32_t)((cb + khB) ^ l7) << 4));
            ldsm_x4(b[2][0], b[2][1], b[3][0], b[3][1],
                    Bb + boff1 + ((uint32_t)((cb + khB) ^ l7) << 4));
            #pragma unroll
            for (int mt = 0; mt < 2; mt++)
                #pragma unroll
                for (int nt = 0; nt < 4; nt++)
                    mma16816(acc[mt][nt][0], acc[mt][nt][1], acc[mt][nt][2], acc[mt][nt][3],
                             a[mt][0], a[mt][1], a[mt][2], a[mt][3], b[nt][0], b[nt][1]);
        }

        // ---- chunk complete (K done): shift-free softmax accumulation ----
        if ((t & 3) == 3) {
            const int nh = t >> 2;
            const bool dhit = (nh == nh_d) && (wn == dwn) && ((lane & 3) == down);
            #pragma unroll
            for (int mt = 0; mt < 2; mt++) {
                #pragma unroll
                for (int h = 0; h < 2; h++) {
                    const int si = mt * 2 + h;
                    float add = 0.f;
                    #pragma unroll
                    for (int nt = 0; nt < 4; nt++) {
                        const float v0 = fmaf(Wv, acc[mt][nt][h * 2 + 0], Bv);
                        const float v1 = fmaf(Wv, acc[mt][nt][h * 2 + 1], Bv);
                        add += __expf(v0) + __expf(v1);
                        if (dhit && nt == dnt) od[si] += (de ? v1 : v0);
                    }
                    os[si] += add;
                }
            }
        }

        __syncthreads();                 // all warps done with slot t&1
        if (t + 2 < 16) load_round(sb, t + 2, tid, bi);   // overlaps round t+1
    }

    // ---- combine sums across the 4 lanes of each row quad ----
    #pragma unroll
    for (int si = 0; si < 4; si++) {
        #pragma unroll
        for (int off = 1; off <= 2; off <<= 1) {
            os[si] += __shfl_xor_sync(0xffffffffu, os[si], off);
            od[si] += __shfl_xor_sync(0xffffffffu, od[si], off);
        }
    }

    // ---- merge the 4 column-stripe warps per row-half via smem ----
    float* sm_s = (float*)smem;            // [8][32]  (GEMM smem dead now)
    float* sm_d = sm_s + 256;              // [8][32]
    float* sm_r = sm_d + 256;              // partials
    __syncthreads();
    if ((lane & 3) == 0) {
        #pragma unroll
        for (int si = 0; si < 4; si++) {
            const int r = (si >> 1) * 16 + (si & 1) * 8 + (lane >> 2);
            sm_s[wid * 32 + r] = os[si];
            sm_d[wid * 32 + r] = od[si];
        }
    }
    __syncthreads();

    if (wid < 2) {   // warp wid merges rows of half wm=wid from stripes wid*4..wid*4+3
        float s = 0.f, d = 0.f;
        #pragma unroll
        for (int p = 0; p < 4; p++) {
            s += sm_s[(wid * 4 + p) * 32 + lane];
            d += sm_d[(wid * 4 + p) * 32 + lane];
        }
        float local = d - __logf(s);
        #pragma unroll
        for (int o = 16; o > 0; o >>= 1)
            local += __shfl_xor_sync(0xffffffffu, local, o);
        if (lane == 0) sm_r[wid] = local;
    }
    __syncthreads();

    // ---- fused finalize: last block deterministically reduces g_part ----
    if (tid == 0) {
        g_part[bi] = sm_r[0] + sm_r[1];
        __threadfence();
        lastflag = (atomicAdd(&g_ctr, 1) == 255);
    }
    __syncthreads();
    if (lastflag) {
        float t = g_part[tid];
        #pragma unroll
        for (int o = 16; o > 0; o >>= 1)
            t += __shfl_xor_sync(0xffffffffu, t, o);
        if (lane == 0) sm_r[8 + wid] = t;
        __syncthreads();
        if (tid == 0) {
            float tt = 0.f;
            #pragma unroll
            for (int i = 0; i < 8; i++) tt += sm_r[8 + i];
            out[0] = -tt * (1.0f / (float)NU);
            g_ctr = 0;   // reset for next graph replay
        }
    }
}

extern "C" void kernel_launch(void* const* d_in, const int* in_sizes, int n_in,
                              void* d_out, int out_size) {
    const float* emb = (const float*)d_in[0];
    const float* w = (const float*)d_in[1];
    const float* b = (const float*)d_in[2];
    float* out = (float*)d_out;

    cudaFuncSetAttribute(prep_kernel, cudaFuncAttributeMaxDynamicSharedMemorySize, 65536);
    cudaFuncSetAttribute(gemm_loss_kernel, cudaFuncAttributeMaxDynamicSharedMemorySize, SM_TOT);

    prep_kernel<<<NSPK, 256, 65536>>>(emb);
    gemm_loss_kernel<<<256, 256, SM_TOT>>>(w, b, out);
}